// round 2
// baseline (speedup 1.0000x reference)
#include <cuda_runtime.h>
#include <cstdint>

// Fused hinge-loss + mean reduction.
//   hinge = relu(lo - x)^2 + relu(x - hi)^2, lo/hi from affine SEG ramp:
//   hi = 1 - 0.25*y, lo = hi - 0.25; valid iff 0 <= y < 4.
//   out = mean(Loss + hinge*valid)
//
// NOTE: y is int32 on device (JAX silently downgrades int64 without x64 mode).
//
// Stage 1: grid-stride vectorized partial sums -> g_partials[block]
// Stage 2: single block sums partials deterministically, adds scalar tail,
//          divides by n.

#define RED_BLOCKS 1024
#define RED_THREADS 256

__device__ float g_partials[RED_BLOCKS];

__device__ __forceinline__ float hinge_term(float xv, int yv) {
    bool valid = ((unsigned)yv < 4u);           // 0 <= y < 4
    int yc = valid ? yv : 0;
    float hi = fmaf((float)yc, -0.25f, 1.0f);   // SEG[y]   = 1 - 0.25*y
    float lo = hi - 0.25f;                      // SEG[y+1]
    float amin = fmaxf(lo - xv, 0.0f);
    float amax = fmaxf(xv - hi, 0.0f);
    float h = fmaf(amin, amin, amax * amax);
    return valid ? h : 0.0f;
}

__global__ void __launch_bounds__(RED_THREADS)
hinge_partial_kernel(const float* __restrict__ x,
                     const int* __restrict__ y,
                     const float* __restrict__ L,
                     long long nvec)   // number of float4 groups
{
    const float4* __restrict__ x4 = (const float4*)x;
    const float4* __restrict__ L4 = (const float4*)L;
    const int4*   __restrict__ y4 = (const int4*)y;

    float acc = 0.0f;
    long long stride = (long long)gridDim.x * blockDim.x;
    long long i = (long long)blockIdx.x * blockDim.x + threadIdx.x;

    #pragma unroll 4
    for (; i < nvec; i += stride) {
        float4 xv = x4[i];
        float4 lv = L4[i];
        int4   yv = y4[i];

        float s;
        s  = lv.x + hinge_term(xv.x, yv.x);
        s += lv.y + hinge_term(xv.y, yv.y);
        s += lv.z + hinge_term(xv.z, yv.z);
        s += lv.w + hinge_term(xv.w, yv.w);
        acc += s;
    }

    // warp reduce
    #pragma unroll
    for (int off = 16; off > 0; off >>= 1)
        acc += __shfl_xor_sync(0xFFFFFFFFu, acc, off);

    __shared__ float warp_sums[RED_THREADS / 32];
    int lane = threadIdx.x & 31;
    int wid  = threadIdx.x >> 5;
    if (lane == 0) warp_sums[wid] = acc;
    __syncthreads();

    if (wid == 0) {
        float v = (lane < RED_THREADS / 32) ? warp_sums[lane] : 0.0f;
        #pragma unroll
        for (int off = 16; off > 0; off >>= 1)
            v += __shfl_xor_sync(0xFFFFFFFFu, v, off);
        if (lane == 0) g_partials[blockIdx.x] = v;
    }
}

__global__ void __launch_bounds__(RED_THREADS)
hinge_finalize_kernel(const float* __restrict__ x,
                      const int* __restrict__ y,
                      const float* __restrict__ L,
                      long long n, long long nvec,
                      float* __restrict__ out)
{
    // fixed-order sum over block partials -> deterministic
    float acc = 0.0f;
    for (int i = threadIdx.x; i < RED_BLOCKS; i += RED_THREADS)
        acc += g_partials[i];

    #pragma unroll
    for (int off = 16; off > 0; off >>= 1)
        acc += __shfl_xor_sync(0xFFFFFFFFu, acc, off);

    __shared__ float warp_sums[RED_THREADS / 32];
    int lane = threadIdx.x & 31;
    int wid  = threadIdx.x >> 5;
    if (lane == 0) warp_sums[wid] = acc;
    __syncthreads();

    if (threadIdx.x == 0) {
        float total = 0.0f;
        #pragma unroll
        for (int w = 0; w < RED_THREADS / 32; w++) total += warp_sums[w];
        // scalar tail (n % 4 != 0)
        for (long long i = nvec * 4; i < n; i++)
            total += L[i] + hinge_term(x[i], y[i]);
        out[0] = total / (float)n;
    }
}

extern "C" void kernel_launch(void* const* d_in, const int* in_sizes, int n_in,
                              void* d_out, int out_size)
{
    const float* x = (const float*)d_in[0];
    const int*   y = (const int*)d_in[1];
    const float* L = (const float*)d_in[2];
    float* out = (float*)d_out;

    long long n = (long long)in_sizes[0];
    long long nvec = n >> 2;   // float4 groups

    hinge_partial_kernel<<<RED_BLOCKS, RED_THREADS>>>(x, y, L, nvec);
    hinge_finalize_kernel<<<1, RED_THREADS>>>(x, y, L, n, nvec, out);
}